// round 2
// baseline (speedup 1.0000x reference)
#include <cuda_runtime.h>
#include <cstdint>

// Problem constants: B=32, N=1024, K=16, D=256, L=256
#define ROWS_TOTAL 32768
#define D_DIM 256
#define L_DIM 256
#define KNBR 16

#define TM 64                 // rows per CTA
#define KC 16                 // k-chunk for W staging
#define PAD 4
#define SROW (TM + PAD)       // 68 floats: 272B = 17*16 -> float4-aligned rows

// smem: sT[256][SROW] + wbuf[KC][256] + invf[TM]
#define SMEM_FLOATS (D_DIM * SROW + KC * L_DIM + TM)
#define SMEM_BYTES  (SMEM_FLOATS * 4)

__global__ void __launch_bounds__(256, 2) gcn_fused_kernel(
    const float* __restrict__ targets,
    const float* __restrict__ neighbors,
    const float* __restrict__ avec,
    const float* __restrict__ W,
    float* __restrict__ out)
{
    extern __shared__ float smem[];
    float* sT   = smem;                       // [D_DIM][SROW]  (d-major, transposed)
    float* wbuf = sT + D_DIM * SROW;          // [KC][L_DIM]
    float* invf = wbuf + KC * L_DIM;          // [TM]

    const int tid  = threadIdx.x;
    const int row0 = blockIdx.x * TM;

    // ---- degree factor (folded into s; division commutes with linear map) ----
    if (tid < TM) {
        const float* ap = avec + (size_t)(row0 + tid) * (KNBR + 1);
        float f = 0.f;
#pragma unroll
        for (int j = 0; j < KNBR + 1; j++) f += ap[j];
        invf[tid] = (f > 0.5f) ? (1.0f / f) : 1.0f;
    }
    __syncthreads();

    // ---- reduction: s[row][d] = targets + sum_k neighbors, * invf ----
    // thread t owns d = t; fully coalesced 128B/warp global loads.
    {
        const int d = tid;
        for (int r = 0; r < TM; r++) {
            const int row = row0 + r;
            const float* np = neighbors + (size_t)row * (KNBR * D_DIM) + d;
            float acc = targets[(size_t)row * D_DIM + d];
#pragma unroll
            for (int k = 0; k < KNBR; k++) acc += np[k * D_DIM];
            sT[d * SROW + r] = acc * invf[r];
        }
    }

    // ---- GEMM: out[64 x 256] = sT^T @ W, relu ----
    const int ty = tid >> 5;          // 0..7 -> row group
    const int tx = tid & 31;          // 0..31 -> col group
    const int r0 = ty * 8;
    // thread's columns: pairs at c = 2*tx + 64*j, j=0..3 (warp-contiguous)

    unsigned long long acc[8][4];
#pragma unroll
    for (int i = 0; i < 8; i++)
#pragma unroll
        for (int j = 0; j < 4; j++) acc[i][j] = 0ull;

    for (int kc = 0; kc < D_DIM; kc += KC) {
        __syncthreads();   // also separates reduction writes from first GEMM reads
        // stage W[kc..kc+15][0..255] -> wbuf (L2-resident source)
#pragma unroll
        for (int v = 0; v < 4; v++) {
            int f4 = v * 256 + tid;        // float4 index into 16x256 chunk
            int wr = f4 >> 6;              // 64 float4 per row
            int wc = (f4 & 63) << 2;
            *(float4*)&wbuf[wr * L_DIM + wc] =
                *(const float4*)&W[(size_t)(kc + wr) * L_DIM + wc];
        }
        __syncthreads();

#pragma unroll
        for (int kk = 0; kk < KC; kk++) {
            // A: 8 rows, warp-broadcast LDS.128 (all lanes same address)
            const float* srow = &sT[(kc + kk) * SROW + r0];
            float4 a0 = *(const float4*)(srow);
            float4 a1 = *(const float4*)(srow + 4);
            float av[8] = {a0.x, a0.y, a0.z, a0.w, a1.x, a1.y, a1.z, a1.w};

            // B: 4 f32x2 pairs, warp-contiguous LDS.64
            unsigned long long bp[4];
#pragma unroll
            for (int j = 0; j < 4; j++)
                bp[j] = *(const unsigned long long*)&wbuf[kk * L_DIM + 2 * tx + 64 * j];

#pragma unroll
            for (int i = 0; i < 8; i++) {
                unsigned long long ap2;
                unsigned au = __float_as_uint(av[i]);
                asm("mov.b64 %0, {%1, %1};" : "=l"(ap2) : "r"(au));
#pragma unroll
                for (int j = 0; j < 4; j++)
                    asm("fma.rn.f32x2 %0, %1, %2, %0;"
                        : "+l"(acc[i][j]) : "l"(ap2), "l"(bp[j]));
            }
        }
    }

    // ---- epilogue: relu + coalesced float2 stores (256B contiguous per warp) ----
#pragma unroll
    for (int i = 0; i < 8; i++) {
        const size_t rbase = (size_t)(row0 + r0 + i) * L_DIM;
#pragma unroll
        for (int j = 0; j < 4; j++) {
            unsigned lo_u, hi_u;
            asm("mov.b64 {%0, %1}, %2;" : "=r"(lo_u), "=r"(hi_u) : "l"(acc[i][j]));
            float2 v;
            v.x = fmaxf(__uint_as_float(lo_u), 0.f);
            v.y = fmaxf(__uint_as_float(hi_u), 0.f);
            *(float2*)&out[rbase + 2 * tx + 64 * j] = v;
        }
    }
}

extern "C" void kernel_launch(void* const* d_in, const int* in_sizes, int n_in,
                              void* d_out, int out_size)
{
    const float* targets   = (const float*)d_in[0];
    const float* neighbors = (const float*)d_in[1];
    const float* avec      = (const float*)d_in[2];
    const float* W         = (const float*)d_in[3];
    float* out             = (float*)d_out;

    (void)in_sizes; (void)n_in; (void)out_size;

    cudaFuncSetAttribute(gcn_fused_kernel,
                         cudaFuncAttributeMaxDynamicSharedMemorySize, SMEM_BYTES);

    const int blocks = ROWS_TOTAL / TM;   // 512
    gcn_fused_kernel<<<blocks, 256, SMEM_BYTES>>>(targets, neighbors, avec, W, out);
}

// round 4
// speedup vs baseline: 1.1901x; 1.1901x over previous
#include <cuda_runtime.h>
#include <cstdint>

// Problem constants: B=32, N=1024, K=16, D=256, L=256
#define ROWS_TOTAL 32768
#define D_DIM 256
#define L_DIM 256
#define KNBR 16

#define TM 64                  // rows per CTA tile
#define KC 16                  // d-chunk size (pipeline granularity)
#define NCHUNK (D_DIM / KC)    // 16
#define SROW 68                // padded row: 68*4B = 272B = 17*16B (float4-aligned)

// named barrier ids: 1,2 = "buffer b full", 3,4 = "buffer b free" (0 reserved)
#define BAR_SYNC(id)   asm volatile("bar.sync %0, 512;"   :: "r"(id))
#define BAR_ARRIVE(id) asm volatile("bar.arrive %0, 512;" :: "r"(id))

__global__ void __launch_bounds__(512, 1) gcn_ws_kernel(
    const float* __restrict__ targets,
    const float* __restrict__ neighbors,
    const float* __restrict__ avec,
    const float* __restrict__ W,
    float* __restrict__ out)
{
    __shared__ float sTb[2][KC][SROW];     // reduced chunk, d-major transposed
    __shared__ float wbuf[2][KC][L_DIM];   // W chunk

    const int tid  = threadIdx.x;
    const int row0 = blockIdx.x * TM;

    if (tid < 256) {
        // ================= PRODUCER (warps 0..7) =================
        const int r   = tid >> 2;          // 0..63 : row within tile
        const int q   = tid & 3;           // 0..3  : float4 quad within 16-d chunk
        const int row = row0 + r;

        // per-thread degree factor (redundant x4, trivial cost; no barrier needed)
        const float* ap = avec + (size_t)row * (KNBR + 1);
        float f = 0.f;
#pragma unroll
        for (int j = 0; j < KNBR + 1; j++) f += ap[j];
        const float inv = (f > 0.5f) ? (1.0f / f) : 1.0f;

        const float* tgt = targets   + (size_t)row * D_DIM;
        const float* nb  = neighbors + (size_t)row * (KNBR * D_DIM);

        for (int c = 0; c < NCHUNK; c++) {
            const int b = c & 1;
            if (c >= 2) BAR_SYNC(3 + b);            // wait: buffer freed by consumers

            // stage W rows [c*16 .. c*16+16) -> wbuf[b]  (L2-resident source)
#pragma unroll
            for (int v = 0; v < 4; v++) {
                int f4 = v * 256 + tid;             // float4 index into 16x256 chunk
                int wr = f4 >> 6;                   // 64 float4 per row
                int wc = (f4 & 63) << 2;
                *(float4*)&wbuf[b][wr][wc] =
                    *(const float4*)&W[(size_t)(c * KC + wr) * L_DIM + wc];
            }

            // reduce: s[row][d] = (targets + sum_k neighbors) * inv, d in quad
            const int dbase = c * KC + 4 * q;
            float4 acc = *(const float4*)&tgt[dbase];
#pragma unroll
            for (int k = 0; k < KNBR; k++) {
                float4 v = *(const float4*)&nb[k * D_DIM + dbase];
                acc.x += v.x; acc.y += v.y; acc.z += v.z; acc.w += v.w;
            }
            acc.x *= inv; acc.y *= inv; acc.z *= inv; acc.w *= inv;

            // transposed store (2-way bank conflict max, negligible)
            sTb[b][4 * q + 0][r] = acc.x;
            sTb[b][4 * q + 1][r] = acc.y;
            sTb[b][4 * q + 2][r] = acc.z;
            sTb[b][4 * q + 3][r] = acc.w;

            __threadfence_block();                  // make STS visible pre-arrive
            BAR_ARRIVE(1 + b);                      // signal: buffer full
        }
    } else {
        // ================= CONSUMER (warps 8..15) =================
        const int ct = tid - 256;
        const int ty = ct >> 5;            // 0..7 -> row group of 8
        const int tx = ct & 31;            // cols: pairs at 2*tx + 64*j
        const int r0 = ty * 8;

        unsigned long long acc[8][4];
#pragma unroll
        for (int i = 0; i < 8; i++)
#pragma unroll
            for (int j = 0; j < 4; j++) acc[i][j] = 0ull;

        for (int c = 0; c < NCHUNK; c++) {
            const int b = c & 1;
            BAR_SYNC(1 + b);                        // wait: buffer full

#pragma unroll
            for (int kk = 0; kk < KC; kk++) {
                // A: 8 rows via two warp-broadcast LDS.128
                const float* srow = &sTb[b][kk][r0];
                float4 a0 = *(const float4*)(srow);
                float4 a1 = *(const float4*)(srow + 4);
                float av[8] = {a0.x, a0.y, a0.z, a0.w, a1.x, a1.y, a1.z, a1.w};

                // B: 4 f32x2 pairs, warp-contiguous LDS.64
                unsigned long long bp[4];
#pragma unroll
                for (int j = 0; j < 4; j++)
                    bp[j] = *(const unsigned long long*)&wbuf[b][kk][2 * tx + 64 * j];

#pragma unroll
                for (int i = 0; i < 8; i++) {
                    unsigned long long ap2;
                    unsigned au = __float_as_uint(av[i]);
                    asm("mov.b64 %0, {%1, %1};" : "=l"(ap2) : "r"(au));
#pragma unroll
                    for (int j = 0; j < 4; j++)
                        asm("fma.rn.f32x2 %0, %1, %2, %0;"
                            : "+l"(acc[i][j]) : "l"(ap2), "l"(bp[j]));
                }
            }

            BAR_ARRIVE(3 + b);                      // signal: buffer free
        }

        // epilogue: relu + coalesced float2 stores (256B contiguous per warp)
#pragma unroll
        for (int i = 0; i < 8; i++) {
            const size_t rbase = (size_t)(row0 + r0 + i) * L_DIM;
#pragma unroll
            for (int j = 0; j < 4; j++) {
                unsigned lo_u, hi_u;
                asm("mov.b64 {%0, %1}, %2;" : "=r"(lo_u), "=r"(hi_u) : "l"(acc[i][j]));
                float2 v;
                v.x = fmaxf(__uint_as_float(lo_u), 0.f);
                v.y = fmaxf(__uint_as_float(hi_u), 0.f);
                *(float2*)&out[rbase + 2 * tx + 64 * j] = v;
            }
        }
    }
}

extern "C" void kernel_launch(void* const* d_in, const int* in_sizes, int n_in,
                              void* d_out, int out_size)
{
    const float* targets   = (const float*)d_in[0];
    const float* neighbors = (const float*)d_in[1];
    const float* avec      = (const float*)d_in[2];
    const float* W         = (const float*)d_in[3];
    float* out             = (float*)d_out;

    (void)in_sizes; (void)n_in; (void)out_size;

    const int blocks = ROWS_TOTAL / TM;   // 512
    gcn_ws_kernel<<<blocks, 512>>>(targets, neighbors, avec, W, out);
}